// round 11
// baseline (speedup 1.0000x reference)
#include <cuda_runtime.h>
#include <cuda_bf16.h>
#include <math.h>
#include <stdint.h>

// Problem constants (B=32, S=512, H=2048, FP=SP=1024)
#define NTOK 16384
#define HDIM 2048
#define CDIM 1024
#define OUTW 2050

// GEMM tiling (mma.sync path)
#define BM 128
#define BN 128
#define BK 64                   // bf16 elems per K-stage = 128 bytes/row
#define KT (HDIM / BK)          // 32
#define SPLIT_SZ 16384          // 128 rows x 128 bytes
#define STAGE_SZ (4 * SPLIT_SZ) // Ah, Al, Bh, Bl = 64 KB
#define NSTAGE 3
#define NTILES (CDIM / BN)      // 8 n-tiles per m-tile

// ---------------------------------------------------------------------------
// Scratch (allocation-free: __device__ globals)
// ---------------------------------------------------------------------------
__device__ float g_logits[2][(size_t)NTOK * CDIM];
__device__ __nv_bfloat16 g_Ahi[2][(size_t)NTOK * HDIM];
__device__ __nv_bfloat16 g_Alo[2][(size_t)NTOK * HDIM];
__device__ __nv_bfloat16 g_Whi[2][(size_t)CDIM * HDIM];
__device__ __nv_bfloat16 g_Wlo[2][(size_t)CDIM * HDIM];
__device__ int   g_list[2][NTOK];
__device__ int   g_cnt[2];
__device__ int   g_done[2][NTOK / BM];   // per (class, m-tile) n-tile completion count
__device__ float g_nonend[NTOK];

// ---------------------------------------------------------------------------
// helpers
// ---------------------------------------------------------------------------
__device__ __forceinline__ uint32_t smem_u32(const void* p) {
    uint32_t a;
    asm("{ .reg .u64 t; cvta.to.shared.u64 t, %1; cvt.u32.u64 %0, t; }" : "=r"(a) : "l"(p));
    return a;
}
__device__ __forceinline__ uint32_t swz128(uint32_t o) { return o ^ ((o >> 3) & 0x70); }
__device__ __forceinline__ void cp16(uint32_t dst, const void* src) {
    asm volatile("cp.async.cg.shared.global [%0], [%1], 16;" :: "r"(dst), "l"(src));
}
__device__ __forceinline__ void cp_commit() { asm volatile("cp.async.commit_group;" ::: "memory"); }
template <int N> __device__ __forceinline__ void cp_wait() {
    asm volatile("cp.async.wait_group %0;" :: "n"(N) : "memory");
}
__device__ __forceinline__ void ldsm4(uint32_t* r, uint32_t addr) {
    asm volatile("ldmatrix.sync.aligned.m8n8.x4.shared.b16 {%0,%1,%2,%3}, [%4];"
                 : "=r"(r[0]), "=r"(r[1]), "=r"(r[2]), "=r"(r[3]) : "r"(addr));
}
__device__ __forceinline__ void hmma(float* c, const uint32_t* a, uint32_t b0, uint32_t b1) {
    asm volatile("mma.sync.aligned.m16n8k16.row.col.f32.bf16.bf16.f32 "
                 "{%0,%1,%2,%3}, {%4,%5,%6,%7}, {%8,%9}, {%0,%1,%2,%3};"
                 : "+f"(c[0]), "+f"(c[1]), "+f"(c[2]), "+f"(c[3])
                 : "r"(a[0]), "r"(a[1]), "r"(a[2]), "r"(a[3]), "r"(b0), "r"(b1));
}
__device__ __forceinline__ void split2(float a, float b, uint32_t& hi, uint32_t& lo) {
    __nv_bfloat162 h = __floats2bfloat162_rn(a, b);
    float2 hf = __bfloat1622float2(h);
    __nv_bfloat162 l = __floats2bfloat162_rn(a - hf.x, b - hf.y);
    hi = *reinterpret_cast<uint32_t*>(&h);
    lo = *reinterpret_cast<uint32_t*>(&l);
}

// ---------------------------------------------------------------------------
// Kernel 0: reset counters (every replay)
// ---------------------------------------------------------------------------
__global__ void k_reset() {
    const int tid = threadIdx.x;
    if (tid < 2) g_cnt[tid] = 0;
    if (tid < 2 * (NTOK / BM)) g_done[tid / (NTOK / BM)][tid % (NTOK / BM)] = 0;
}

// ---------------------------------------------------------------------------
// Kernel 1: end head + classification + list build + FUSED X-split.
// Zero-fill for class-1/2 token rows moved into the fused GEMM softmax tail.
// ---------------------------------------------------------------------------
__global__ __launch_bounds__(256) void k_classify(
    const float* __restrict__ X, const int* __restrict__ pY,
    const float* __restrict__ W_end, const float* __restrict__ b_end,
    float* __restrict__ out)
{
    const int warp = threadIdx.x >> 5;
    const int lane = threadIdx.x & 31;
    const int t = blockIdx.x * 8 + warp;
    if (t >= NTOK) return;

    const float4* x4 = reinterpret_cast<const float4*>(X + (size_t)t * HDIM);
    const float4* w4 = reinterpret_cast<const float4*>(W_end);
    float s = 0.f;
    #pragma unroll
    for (int i = 0; i < 16; ++i) {
        float4 a = x4[lane + 32 * i];
        float4 b = w4[lane + 32 * i];
        s += a.x * b.x + a.y * b.y + a.z * b.z + a.w * b.w;
    }
    #pragma unroll
    for (int o = 16; o; o >>= 1) s += __shfl_xor_sync(0xffffffffu, s, o);
    const float logit = s + b_end[0];
    const float p = 1.f / (1.f + expf(-logit));

    if (lane == 0) g_nonend[t] = 1.f - p;

    const int c = pY[t];
    float* lp  = out;
    float* row = out + NTOK + (size_t)t * OUTW;

    if (c == 0) {
        if (lane == 0) { lp[t] = logf(p); row[0] = p; row[1] = p; }
        for (int i = 2 + lane; i < OUTW; i += 32) row[i] = 0.f;
    } else if (c == 1 || c == 2) {
        const int z = c - 1;
        int q = 0;
        if (lane == 0) { q = atomicAdd(&g_cnt[z], 1); g_list[z][q] = t; }
        q = __shfl_sync(0xffffffffu, q, 0);
        uint2* dh = reinterpret_cast<uint2*>(g_Ahi[z] + (size_t)q * HDIM);
        uint2* dl = reinterpret_cast<uint2*>(g_Alo[z] + (size_t)q * HDIM);
        #pragma unroll
        for (int i = 0; i < 16; ++i) {
            float4 v = x4[lane + 32 * i];
            uint32_t h0, l0, h1, l1;
            split2(v.x, v.y, h0, l0);
            split2(v.z, v.w, h1, l1);
            dh[lane + 32 * i] = make_uint2(h0, h1);
            dl[lane + 32 * i] = make_uint2(l0, l1);
        }
        // row zero-fill + probs done by the fused GEMM softmax tail
    } else {
        if (lane == 0) lp[t] = 0.f;
        for (int i = lane; i < OUTW; i += 32) row[i] = 0.f;
    }
}

// ---------------------------------------------------------------------------
// Kernel 2: MERGED weight split (blocks [0,256)) + A pad-row zeroing
// (blocks [256,272)). Runs after k_classify (pad part needs g_cnt).
// ---------------------------------------------------------------------------
__global__ __launch_bounds__(256) void k_convert_w_pad(
    const float* __restrict__ W_hcw, const float* __restrict__ W_roo)
{
    const int z = blockIdx.y;
    const int warp = threadIdx.x >> 5, lane = threadIdx.x & 31;

    if (blockIdx.x < 2 * CDIM / 8) {
        const int half = blockIdx.x * 8 + warp;        // 0 .. 2*CDIM-1
        const int rowi = half >> 1;
        const int off  = (half & 1) * 256;             // float4 offset within row
        const float* W = z ? W_roo : W_hcw;
        const float4* s = reinterpret_cast<const float4*>(W + (size_t)rowi * HDIM) + off;
        uint2* dh = reinterpret_cast<uint2*>(g_Whi[z] + (size_t)rowi * HDIM) + off;
        uint2* dl = reinterpret_cast<uint2*>(g_Wlo[z] + (size_t)rowi * HDIM) + off;
        #pragma unroll
        for (int i = 0; i < 8; ++i) {
            float4 v = s[lane + 32 * i];
            uint32_t h0, l0, h1, l1;
            split2(v.x, v.y, h0, l0);
            split2(v.z, v.w, h1, l1);
            dh[lane + 32 * i] = make_uint2(h0, h1);
            dl[lane + 32 * i] = make_uint2(l0, l1);
        }
    } else {
        const int cnt = g_cnt[z];
        const int pad = (cnt + BM - 1) & ~(BM - 1);
        const int pos = cnt + (blockIdx.x - 2 * CDIM / 8) * 8 + warp;
        if (pos >= pad) return;
        uint2* dh = reinterpret_cast<uint2*>(g_Ahi[z] + (size_t)pos * HDIM);
        uint2* dl = reinterpret_cast<uint2*>(g_Alo[z] + (size_t)pos * HDIM);
        #pragma unroll
        for (int i = 0; i < 16; ++i) {
            dh[lane + 32 * i] = make_uint2(0u, 0u);
            dl[lane + 32 * i] = make_uint2(0u, 0u);
        }
    }
}

// ---------------------------------------------------------------------------
// Kernel 3: split-bf16 GEMM (R10 mainloop, unchanged) + FUSED softmax tail.
// The CTA completing the 8th n-tile of an m-tile runs softmax + scatter +
// zero-spans + log_prob for those 128 rows (logits L2-hot).
// ---------------------------------------------------------------------------
__device__ __forceinline__ void load_stage(int z, int m0, int n0, int k0,
                                           uint32_t sbase, int tid)
{
    const __nv_bfloat16* Ah = g_Ahi[z];
    const __nv_bfloat16* Al = g_Alo[z];
    const __nv_bfloat16* Bh = g_Whi[z];
    const __nv_bfloat16* Bl = g_Wlo[z];
    #pragma unroll
    for (int i = 0; i < 4; ++i) {
        int c = tid + 256 * i;
        int r = c >> 3, cc = c & 7;
        uint32_t off = swz128((uint32_t)(r * 128 + cc * 16));
        size_t ga = (size_t)(m0 + r) * HDIM + k0 + cc * 8;
        size_t gb = (size_t)(n0 + r) * HDIM + k0 + cc * 8;
        cp16(sbase + off,                Ah + ga);
        cp16(sbase + SPLIT_SZ + off,     Al + ga);
        cp16(sbase + 2 * SPLIT_SZ + off, Bh + gb);
        cp16(sbase + 3 * SPLIT_SZ + off, Bl + gb);
    }
}

__device__ __forceinline__ void load_frags(
    uint32_t Af[2][2][4], uint32_t Bf[2][4][4], uint32_t st, int kb,
    int a_row, int a_kb, int b_row, int b_kb)
{
    #pragma unroll
    for (int i = 0; i < 2; ++i) {
        uint32_t off = swz128((uint32_t)((a_row + i * 16) * 128 + kb + a_kb));
        ldsm4(Af[0][i], st + off);
        ldsm4(Af[1][i], st + SPLIT_SZ + off);
    }
    #pragma unroll
    for (int j = 0; j < 4; ++j) {
        uint32_t off = swz128((uint32_t)((b_row + j * 16) * 128 + kb + b_kb));
        ldsm4(Bf[0][j], st + 2 * SPLIT_SZ + off);
        ldsm4(Bf[1][j], st + 3 * SPLIT_SZ + off);
    }
}

__device__ __forceinline__ void mma_block(
    float acc[2][8][4], uint32_t Af[2][2][4], uint32_t Bf[2][4][4])
{
    #pragma unroll
    for (int i = 0; i < 2; ++i)
        #pragma unroll
        for (int j = 0; j < 8; ++j) {
            const uint32_t bh0 = Bf[0][j >> 1][(j & 1) * 2];
            const uint32_t bh1 = Bf[0][j >> 1][(j & 1) * 2 + 1];
            const uint32_t bl0 = Bf[1][j >> 1][(j & 1) * 2];
            const uint32_t bl1 = Bf[1][j >> 1][(j & 1) * 2 + 1];
            hmma(acc[i][j], Af[0][i], bh0, bh1);   // hi*hi
            hmma(acc[i][j], Af[0][i], bl0, bl1);   // hi*lo
            hmma(acc[i][j], Af[1][i], bh0, bh1);   // lo*hi
        }
}

__global__ __launch_bounds__(256, 1) void k_gemm_mma(
    const int* __restrict__ Y,
    const float* __restrict__ b_hcw, const float* __restrict__ b_roo,
    float* __restrict__ out)
{
    extern __shared__ char dsm[];
    __shared__ int s_last;
    const int z   = blockIdx.z;
    const int cnt = g_cnt[z];
    const int m0  = blockIdx.y * BM;
    if (m0 >= cnt) return;
    const int n0  = blockIdx.x * BN;
    const int tid  = threadIdx.x;
    const int wid  = tid >> 5;
    const int lane = tid & 31;
    const int warpM = wid & 3;
    const int warpN = wid >> 2;

    uint32_t sb = (smem_u32(dsm) + 127u) & ~127u;

    float acc[2][8][4];
    #pragma unroll
    for (int i = 0; i < 2; ++i)
        #pragma unroll
        for (int j = 0; j < 8; ++j)
            #pragma unroll
            for (int q = 0; q < 4; ++q) acc[i][j][q] = 0.f;

    load_stage(z, m0, n0, 0,  sb,            tid); cp_commit();
    load_stage(z, m0, n0, BK, sb + STAGE_SZ, tid); cp_commit();

    const int sub  = lane >> 3;
    const int lrow = lane & 7;
    const int a_row = warpM * 32 + (sub & 1) * 8 + lrow;
    const int a_kb  = (sub >> 1) * 16;
    const int b_row = warpN * 64 + (sub >> 1) * 8 + lrow;
    const int b_kb  = (sub & 1) * 16;

    uint32_t Af[2][2][2][4];   // [buf][split][mtile][4]
    uint32_t Bf[2][2][4][4];   // [buf][split][ntile][4]

    for (int kt = 0; kt < KT; ++kt) {
        if (kt >= KT - 1) cp_wait<0>(); else cp_wait<1>();
        __syncthreads();
        if (kt + 2 < KT) {
            load_stage(z, m0, n0, (kt + 2) * BK, sb + ((kt + 2) % NSTAGE) * STAGE_SZ, tid);
            cp_commit();
        }
        const uint32_t st = sb + (kt % NSTAGE) * STAGE_SZ;

        load_frags(Af[0], Bf[0], st, 0, a_row, a_kb, b_row, b_kb);
        #pragma unroll
        for (int s = 0; s < 4; ++s) {
            const int cur = s & 1;
            if (s < 3)
                load_frags(Af[cur ^ 1], Bf[cur ^ 1], st, (s + 1) * 32,
                           a_row, a_kb, b_row, b_kb);
            mma_block(acc, Af[cur], Bf[cur]);
        }
    }

    // ---- epilogue: store raw logits tile ----
    {
        const int g = lane >> 2, tq = lane & 3;
        float* Lg = g_logits[z];
        #pragma unroll
        for (int i = 0; i < 2; ++i) {
            const int r0 = m0 + warpM * 32 + i * 16 + g;
            #pragma unroll
            for (int j = 0; j < 8; ++j) {
                const int col = n0 + warpN * 64 + j * 8 + 2 * tq;
                if (r0 < cnt)
                    *reinterpret_cast<float2*>(Lg + (size_t)r0 * CDIM + col) =
                        make_float2(acc[i][j][0], acc[i][j][1]);
                if (r0 + 8 < cnt)
                    *reinterpret_cast<float2*>(Lg + (size_t)(r0 + 8) * CDIM + col) =
                        make_float2(acc[i][j][2], acc[i][j][3]);
            }
        }
    }

    // ---- completion count: last n-tile CTA runs softmax for this m-tile ----
    __threadfence();            // make this thread's logit stores device-visible
    __syncthreads();            // all threads' fences done before the atomic
    if (tid == 0) {
        int old = atomicAdd(&g_done[z][blockIdx.y], 1);
        s_last = (old == NTILES - 1);
    }
    __syncthreads();
    if (!s_last) return;
    __threadfence();            // acquire: invalidate L1 before reading peers' logits

    const float* __restrict__ bias = (z == 0) ? b_hcw : b_roo;
    const float4* B4 = reinterpret_cast<const float4*>(bias);

    // 8 warps x 16 rows = 128 rows of this m-tile
    for (int r = 0; r < 16; ++r) {
        const int pos = m0 + wid * 16 + r;
        if (pos >= cnt) continue;
        const int t = g_list[z][pos];

        const float* Lrow = g_logits[z] + (size_t)pos * CDIM;
        const float4* L4 = reinterpret_cast<const float4*>(Lrow);

        float4 v[8];
        float mx = -1e30f;
        #pragma unroll
        for (int i = 0; i < 8; ++i) {
            float4 a = L4[lane + 32 * i];
            float4 b = B4[lane + 32 * i];
            a.x += b.x; a.y += b.y; a.z += b.z; a.w += b.w;
            v[i] = a;
            mx = fmaxf(mx, fmaxf(fmaxf(a.x, a.y), fmaxf(a.z, a.w)));
        }
        #pragma unroll
        for (int o = 16; o; o >>= 1) mx = fmaxf(mx, __shfl_xor_sync(0xffffffffu, mx, o));

        float sum = 0.f;
        #pragma unroll
        for (int i = 0; i < 8; ++i) {
            v[i].x = expf(v[i].x - mx); v[i].y = expf(v[i].y - mx);
            v[i].z = expf(v[i].z - mx); v[i].w = expf(v[i].w - mx);
            sum += (v[i].x + v[i].y) + (v[i].z + v[i].w);
        }
        #pragma unroll
        for (int o = 16; o; o >>= 1) sum += __shfl_xor_sync(0xffffffffu, sum, o);

        const float ne = g_nonend[t];
        const float scale = ne / sum;

        float* rowp = out + NTOK + (size_t)t * OUTW;
        // zero the complement span + scatter probs into this class's block
        if (z == 0) {
            if (lane < 2) rowp[lane] = 0.f;
            for (int i = 2 + CDIM + lane; i < OUTW; i += 32) rowp[i] = 0.f;
        } else {
            for (int i = lane; i < 2 + CDIM; i += 32) rowp[i] = 0.f;
        }
        float* rw = rowp + ((z == 0) ? 2 : 2 + CDIM);
        #pragma unroll
        for (int i = 0; i < 8; ++i) {
            const int c0 = 4 * (lane + 32 * i);
            *reinterpret_cast<float2*>(rw + c0)     = make_float2(v[i].x * scale, v[i].y * scale);
            *reinterpret_cast<float2*>(rw + c0 + 2) = make_float2(v[i].z * scale, v[i].w * scale);
        }

        if (lane == 0) {
            const int yv = Y[t];
            int idx = yv - 2 - ((z == 0) ? 0 : CDIM);
            idx = min(max(idx, 0), CDIM - 1);
            const float li = Lrow[idx] + bias[idx];
            out[t] = (li - mx) - logf(sum) + logf(ne);
        }
    }
}

// ---------------------------------------------------------------------------
// Launcher
// ---------------------------------------------------------------------------
extern "C" void kernel_launch(void* const* d_in, const int* in_sizes, int n_in,
                              void* d_out, int out_size)
{
    const float* X     = (const float*)d_in[0];
    const int*   pY    = (const int*)d_in[1];
    const int*   Y     = (const int*)d_in[2];
    const float* W_end = (const float*)d_in[3];
    const float* b_end = (const float*)d_in[4];
    const float* W_hcw = (const float*)d_in[5];
    const float* b_hcw = (const float*)d_in[6];
    const float* W_roo = (const float*)d_in[7];
    const float* b_roo = (const float*)d_in[8];
    float* out = (float*)d_out;
    (void)in_sizes; (void)n_in; (void)out_size;

    const int dyn = 128 + NSTAGE * STAGE_SZ;   // 196736
    static bool attr_set = false;
    if (!attr_set) {
        cudaFuncSetAttribute(k_gemm_mma, cudaFuncAttributeMaxDynamicSharedMemorySize, dyn);
        attr_set = true;
    }

    k_reset<<<1, 256>>>();
    k_classify<<<NTOK / 8, 256>>>(X, pY, W_end, b_end, out);
    k_convert_w_pad<<<dim3(2 * CDIM / 8 + 16, 2), 256>>>(W_hcw, W_roo);
    k_gemm_mma<<<dim3(NTILES, NTOK / BM, 2), 256, dyn>>>(Y, b_hcw, b_roo, out);
}

// round 13
// speedup vs baseline: 1.0416x; 1.0416x over previous
#include <cuda_runtime.h>
#include <cuda_bf16.h>
#include <math.h>
#include <stdint.h>

// Problem constants (B=32, S=512, H=2048, FP=SP=1024)
#define NTOK 16384
#define HDIM 2048
#define CDIM 1024
#define OUTW 2050

// GEMM tiling (mma.sync path)
#define BM 128
#define BN 128
#define BK 64                   // bf16 elems per K-stage = 128 bytes/row
#define KT (HDIM / BK)          // 32
#define SPLIT_SZ 16384          // 128 rows x 128 bytes
#define STAGE_SZ (4 * SPLIT_SZ) // Ah, Al, Bh, Bl = 64 KB
#define NSTAGE 3

// ---------------------------------------------------------------------------
// Scratch (allocation-free: __device__ globals)
// ---------------------------------------------------------------------------
__device__ float g_logits[2][(size_t)NTOK * CDIM];
__device__ __nv_bfloat16 g_Ahi[2][(size_t)NTOK * HDIM];
__device__ __nv_bfloat16 g_Alo[2][(size_t)NTOK * HDIM];
__device__ __nv_bfloat16 g_Whi[2][(size_t)CDIM * HDIM];
__device__ __nv_bfloat16 g_Wlo[2][(size_t)CDIM * HDIM];
__device__ int   g_list[2][NTOK];
__device__ int   g_cnt[2];
__device__ float g_nonend[NTOK];

// ---------------------------------------------------------------------------
// helpers
// ---------------------------------------------------------------------------
__device__ __forceinline__ uint32_t smem_u32(const void* p) {
    uint32_t a;
    asm("{ .reg .u64 t; cvta.to.shared.u64 t, %1; cvt.u32.u64 %0, t; }" : "=r"(a) : "l"(p));
    return a;
}
__device__ __forceinline__ uint32_t swz128(uint32_t o) { return o ^ ((o >> 3) & 0x70); }
__device__ __forceinline__ void cp16(uint32_t dst, const void* src) {
    asm volatile("cp.async.cg.shared.global [%0], [%1], 16;" :: "r"(dst), "l"(src));
}
__device__ __forceinline__ void cp_commit() { asm volatile("cp.async.commit_group;" ::: "memory"); }
template <int N> __device__ __forceinline__ void cp_wait() {
    asm volatile("cp.async.wait_group %0;" :: "n"(N) : "memory");
}
__device__ __forceinline__ void ldsm4(uint32_t* r, uint32_t addr) {
    asm volatile("ldmatrix.sync.aligned.m8n8.x4.shared.b16 {%0,%1,%2,%3}, [%4];"
                 : "=r"(r[0]), "=r"(r[1]), "=r"(r[2]), "=r"(r[3]) : "r"(addr));
}
__device__ __forceinline__ void hmma(float* c, const uint32_t* a, uint32_t b0, uint32_t b1) {
    asm volatile("mma.sync.aligned.m16n8k16.row.col.f32.bf16.bf16.f32 "
                 "{%0,%1,%2,%3}, {%4,%5,%6,%7}, {%8,%9}, {%0,%1,%2,%3};"
                 : "+f"(c[0]), "+f"(c[1]), "+f"(c[2]), "+f"(c[3])
                 : "r"(a[0]), "r"(a[1]), "r"(a[2]), "r"(a[3]), "r"(b0), "r"(b1));
}
__device__ __forceinline__ void split2(float a, float b, uint32_t& hi, uint32_t& lo) {
    __nv_bfloat162 h = __floats2bfloat162_rn(a, b);
    float2 hf = __bfloat1622float2(h);
    __nv_bfloat162 l = __floats2bfloat162_rn(a - hf.x, b - hf.y);
    hi = *reinterpret_cast<uint32_t*>(&h);
    lo = *reinterpret_cast<uint32_t*>(&l);
}

// ---------------------------------------------------------------------------
// Kernel 0: reset counters
// ---------------------------------------------------------------------------
__global__ void k_reset() {
    if (threadIdx.x < 2) g_cnt[threadIdx.x] = 0;
}

// ---------------------------------------------------------------------------
// Kernel 1: MERGED classify (blocks [0, 2048)) + weight split (blocks
// [2048, 2048+512)). The two halves are mutually independent.
// Classify: end head + list build + zero-fill + fused X hi/lo split.
// Weight: bf16 hi/lo split, half-row per warp (z = (blockIdx.x-2048)>>8).
// A pad rows [cnt, ceil128(cnt)) are intentionally NOT zeroed: GEMM rows are
// independent and pad-row logits are never stored (epilogue/softmax guards).
// ---------------------------------------------------------------------------
__global__ __launch_bounds__(256) void k_prep(
    const float* __restrict__ X, const int* __restrict__ pY,
    const float* __restrict__ W_end, const float* __restrict__ b_end,
    const float* __restrict__ W_hcw, const float* __restrict__ W_roo,
    float* __restrict__ out)
{
    const int warp = threadIdx.x >> 5;
    const int lane = threadIdx.x & 31;

    if (blockIdx.x >= NTOK / 8) {
        // ---- weight split: 512 blocks, 8 half-rows each; 2*CDIM halves/class ----
        const int b = blockIdx.x - NTOK / 8;        // 0..511
        const int z = b >> 8;                       // 0..1
        const int half = (b & 255) * 8 + warp;      // 0 .. 2*CDIM-1
        const int rowi = half >> 1;
        const int off  = (half & 1) * 256;          // float4 offset within row
        const float* W = z ? W_roo : W_hcw;
        const float4* s = reinterpret_cast<const float4*>(W + (size_t)rowi * HDIM) + off;
        uint2* dh = reinterpret_cast<uint2*>(g_Whi[z] + (size_t)rowi * HDIM) + off;
        uint2* dl = reinterpret_cast<uint2*>(g_Wlo[z] + (size_t)rowi * HDIM) + off;
        #pragma unroll
        for (int i = 0; i < 8; ++i) {
            float4 v = s[lane + 32 * i];
            uint32_t h0, l0, h1, l1;
            split2(v.x, v.y, h0, l0);
            split2(v.z, v.w, h1, l1);
            dh[lane + 32 * i] = make_uint2(h0, h1);
            dl[lane + 32 * i] = make_uint2(l0, l1);
        }
        return;
    }

    // ---- classify ----
    const int t = blockIdx.x * 8 + warp;

    const float4* x4 = reinterpret_cast<const float4*>(X + (size_t)t * HDIM);
    const float4* w4 = reinterpret_cast<const float4*>(W_end);
    float s = 0.f;
    #pragma unroll
    for (int i = 0; i < 16; ++i) {
        float4 a = x4[lane + 32 * i];
        float4 b = w4[lane + 32 * i];
        s += a.x * b.x + a.y * b.y + a.z * b.z + a.w * b.w;
    }
    #pragma unroll
    for (int o = 16; o; o >>= 1) s += __shfl_xor_sync(0xffffffffu, s, o);
    const float logit = s + b_end[0];
    const float p = 1.f / (1.f + expf(-logit));

    if (lane == 0) g_nonend[t] = 1.f - p;

    const int c = pY[t];
    float* lp  = out;
    float* row = out + NTOK + (size_t)t * OUTW;

    int z0, z1, z2, z3;
    if (c == 0) {
        if (lane == 0) { lp[t] = logf(p); row[0] = p; row[1] = p; }
        z0 = 2; z1 = OUTW; z2 = 0; z3 = 0;
    } else if (c == 1 || c == 2) {
        const int z = c - 1;
        int q = 0;
        if (lane == 0) { q = atomicAdd(&g_cnt[z], 1); g_list[z][q] = t; }
        q = __shfl_sync(0xffffffffu, q, 0);
        uint2* dh = reinterpret_cast<uint2*>(g_Ahi[z] + (size_t)q * HDIM);
        uint2* dl = reinterpret_cast<uint2*>(g_Alo[z] + (size_t)q * HDIM);
        #pragma unroll
        for (int i = 0; i < 16; ++i) {
            float4 v = x4[lane + 32 * i];
            uint32_t h0, l0, h1, l1;
            split2(v.x, v.y, h0, l0);
            split2(v.z, v.w, h1, l1);
            dh[lane + 32 * i] = make_uint2(h0, h1);
            dl[lane + 32 * i] = make_uint2(l0, l1);
        }
        if (z == 0) { z0 = 0; z1 = 2; z2 = 2 + CDIM; z3 = OUTW; }
        else        { z0 = 0; z1 = 2 + CDIM; z2 = 0; z3 = 0; }
    } else {
        if (lane == 0) lp[t] = 0.f;
        z0 = 0; z1 = OUTW; z2 = 0; z3 = 0;
    }
    for (int i = z0 + lane; i < z1; i += 32) row[i] = 0.f;
    for (int i = z2 + lane; i < z3; i += 32) row[i] = 0.f;
}

// ---------------------------------------------------------------------------
// Kernel 2: split-bf16 GEMM via mma.sync.m16n8k16 (HMMA).  [R10 best, exact]
// 128x128 CTA tile, BK=64, 3-stage cp.async pipeline, single sync per K-iter,
// explicit fragment double-buffering across s-steps.
// Pad rows may contain garbage; their results are never stored.
// ---------------------------------------------------------------------------
__device__ __forceinline__ void load_stage(int z, int m0, int n0, int k0,
                                           uint32_t sbase, int tid)
{
    const __nv_bfloat16* Ah = g_Ahi[z];
    const __nv_bfloat16* Al = g_Alo[z];
    const __nv_bfloat16* Bh = g_Whi[z];
    const __nv_bfloat16* Bl = g_Wlo[z];
    #pragma unroll
    for (int i = 0; i < 4; ++i) {
        int c = tid + 256 * i;
        int r = c >> 3, cc = c & 7;
        uint32_t off = swz128((uint32_t)(r * 128 + cc * 16));
        size_t ga = (size_t)(m0 + r) * HDIM + k0 + cc * 8;
        size_t gb = (size_t)(n0 + r) * HDIM + k0 + cc * 8;
        cp16(sbase + off,                Ah + ga);
        cp16(sbase + SPLIT_SZ + off,     Al + ga);
        cp16(sbase + 2 * SPLIT_SZ + off, Bh + gb);
        cp16(sbase + 3 * SPLIT_SZ + off, Bl + gb);
    }
}

__device__ __forceinline__ void load_frags(
    uint32_t Af[2][2][4], uint32_t Bf[2][4][4], uint32_t st, int kb,
    int a_row, int a_kb, int b_row, int b_kb)
{
    #pragma unroll
    for (int i = 0; i < 2; ++i) {
        uint32_t off = swz128((uint32_t)((a_row + i * 16) * 128 + kb + a_kb));
        ldsm4(Af[0][i], st + off);
        ldsm4(Af[1][i], st + SPLIT_SZ + off);
    }
    #pragma unroll
    for (int j = 0; j < 4; ++j) {
        uint32_t off = swz128((uint32_t)((b_row + j * 16) * 128 + kb + b_kb));
        ldsm4(Bf[0][j], st + 2 * SPLIT_SZ + off);
        ldsm4(Bf[1][j], st + 3 * SPLIT_SZ + off);
    }
}

__device__ __forceinline__ void mma_block(
    float acc[2][8][4], uint32_t Af[2][2][4], uint32_t Bf[2][4][4])
{
    #pragma unroll
    for (int i = 0; i < 2; ++i)
        #pragma unroll
        for (int j = 0; j < 8; ++j) {
            const uint32_t bh0 = Bf[0][j >> 1][(j & 1) * 2];
            const uint32_t bh1 = Bf[0][j >> 1][(j & 1) * 2 + 1];
            const uint32_t bl0 = Bf[1][j >> 1][(j & 1) * 2];
            const uint32_t bl1 = Bf[1][j >> 1][(j & 1) * 2 + 1];
            hmma(acc[i][j], Af[0][i], bh0, bh1);   // hi*hi
            hmma(acc[i][j], Af[0][i], bl0, bl1);   // hi*lo
            hmma(acc[i][j], Af[1][i], bh0, bh1);   // lo*hi
        }
}

__global__ __launch_bounds__(256, 1) void k_gemm_mma()
{
    extern __shared__ char dsm[];
    const int z   = blockIdx.z;
    const int cnt = g_cnt[z];
    const int m0  = blockIdx.y * BM;
    if (m0 >= cnt) return;
    const int n0  = blockIdx.x * BN;
    const int tid  = threadIdx.x;
    const int wid  = tid >> 5;
    const int lane = tid & 31;
    const int warpM = wid & 3;
    const int warpN = wid >> 2;

    uint32_t sb = (smem_u32(dsm) + 127u) & ~127u;

    float acc[2][8][4];
    #pragma unroll
    for (int i = 0; i < 2; ++i)
        #pragma unroll
        for (int j = 0; j < 8; ++j)
            #pragma unroll
            for (int q = 0; q < 4; ++q) acc[i][j][q] = 0.f;

    load_stage(z, m0, n0, 0,  sb,            tid); cp_commit();
    load_stage(z, m0, n0, BK, sb + STAGE_SZ, tid); cp_commit();

    const int sub  = lane >> 3;
    const int lrow = lane & 7;
    const int a_row = warpM * 32 + (sub & 1) * 8 + lrow;
    const int a_kb  = (sub >> 1) * 16;
    const int b_row = warpN * 64 + (sub >> 1) * 8 + lrow;
    const int b_kb  = (sub & 1) * 16;

    uint32_t Af[2][2][2][4];   // [buf][split][mtile][4]
    uint32_t Bf[2][2][4][4];   // [buf][split][ntile][4]

    for (int kt = 0; kt < KT; ++kt) {
        if (kt >= KT - 1) cp_wait<0>(); else cp_wait<1>();
        __syncthreads();
        if (kt + 2 < KT) {
            load_stage(z, m0, n0, (kt + 2) * BK, sb + ((kt + 2) % NSTAGE) * STAGE_SZ, tid);
            cp_commit();
        }
        const uint32_t st = sb + (kt % NSTAGE) * STAGE_SZ;

        load_frags(Af[0], Bf[0], st, 0, a_row, a_kb, b_row, b_kb);
        #pragma unroll
        for (int s = 0; s < 4; ++s) {
            const int cur = s & 1;
            if (s < 3)
                load_frags(Af[cur ^ 1], Bf[cur ^ 1], st, (s + 1) * 32,
                           a_row, a_kb, b_row, b_kb);
            mma_block(acc, Af[cur], Bf[cur]);
        }
    }

    const int g = lane >> 2, tq = lane & 3;
    float* Lg = g_logits[z];
    #pragma unroll
    for (int i = 0; i < 2; ++i) {
        const int r0 = m0 + warpM * 32 + i * 16 + g;
        #pragma unroll
        for (int j = 0; j < 8; ++j) {
            const int col = n0 + warpN * 64 + j * 8 + 2 * tq;
            if (r0 < cnt)
                *reinterpret_cast<float2*>(Lg + (size_t)r0 * CDIM + col) =
                    make_float2(acc[i][j][0], acc[i][j][1]);
            if (r0 + 8 < cnt)
                *reinterpret_cast<float2*>(Lg + (size_t)(r0 + 8) * CDIM + col) =
                    make_float2(acc[i][j][2], acc[i][j][3]);
        }
    }
}

// ---------------------------------------------------------------------------
// Kernel 3: softmax + scale by non_end + scatter + log_prob.  [R10 exact]
// ---------------------------------------------------------------------------
__global__ __launch_bounds__(256) void k_softmax(
    const int* __restrict__ Y,
    const float* __restrict__ b_hcw, const float* __restrict__ b_roo,
    float* __restrict__ out)
{
    const int z    = blockIdx.z;
    const int warp = threadIdx.x >> 5;
    const int lane = threadIdx.x & 31;
    const int pos  = blockIdx.x * 8 + warp;
    if (pos >= g_cnt[z]) return;
    const int t = g_list[z][pos];

    const float* __restrict__ bias = (z == 0) ? b_hcw : b_roo;
    const float* Lrow = g_logits[z] + (size_t)pos * CDIM;
    const float4* L4 = reinterpret_cast<const float4*>(Lrow);
    const float4* B4 = reinterpret_cast<const float4*>(bias);

    float4 v[8];
    float mx = -1e30f;
    #pragma unroll
    for (int i = 0; i < 8; ++i) {
        float4 a = L4[lane + 32 * i];
        float4 b = B4[lane + 32 * i];
        a.x += b.x; a.y += b.y; a.z += b.z; a.w += b.w;
        v[i] = a;
        mx = fmaxf(mx, fmaxf(fmaxf(a.x, a.y), fmaxf(a.z, a.w)));
    }
    #pragma unroll
    for (int o = 16; o; o >>= 1) mx = fmaxf(mx, __shfl_xor_sync(0xffffffffu, mx, o));

    float sum = 0.f;
    #pragma unroll
    for (int i = 0; i < 8; ++i) {
        v[i].x = expf(v[i].x - mx); v[i].y = expf(v[i].y - mx);
        v[i].z = expf(v[i].z - mx); v[i].w = expf(v[i].w - mx);
        sum += (v[i].x + v[i].y) + (v[i].z + v[i].w);
    }
    #pragma unroll
    for (int o = 16; o; o >>= 1) sum += __shfl_xor_sync(0xffffffffu, sum, o);

    const float ne = g_nonend[t];
    const float scale = ne / sum;

    float* row = out + NTOK + (size_t)t * OUTW + ((z == 0) ? 2 : 2 + CDIM);
    #pragma unroll
    for (int i = 0; i < 8; ++i) {
        const int c0 = 4 * (lane + 32 * i);
        *reinterpret_cast<float2*>(row + c0)     = make_float2(v[i].x * scale, v[i].y * scale);
        *reinterpret_cast<float2*>(row + c0 + 2) = make_float2(v[i].z * scale, v[i].w * scale);
    }

    if (lane == 0) {
        const int yv = Y[t];
        int idx = yv - 2 - ((z == 0) ? 0 : CDIM);
        idx = min(max(idx, 0), CDIM - 1);
        const float li = Lrow[idx] + bias[idx];
        out[t] = (li - mx) - logf(sum) + logf(ne);
    }
}

// ---------------------------------------------------------------------------
// Launcher
// ---------------------------------------------------------------------------
extern "C" void kernel_launch(void* const* d_in, const int* in_sizes, int n_in,
                              void* d_out, int out_size)
{
    const float* X     = (const float*)d_in[0];
    const int*   pY    = (const int*)d_in[1];
    const int*   Y     = (const int*)d_in[2];
    const float* W_end = (const float*)d_in[3];
    const float* b_end = (const float*)d_in[4];
    const float* W_hcw = (const float*)d_in[5];
    const float* b_hcw = (const float*)d_in[6];
    const float* W_roo = (const float*)d_in[7];
    const float* b_roo = (const float*)d_in[8];
    float* out = (float*)d_out;
    (void)in_sizes; (void)n_in; (void)out_size;

    const int dyn = 128 + NSTAGE * STAGE_SZ;   // 196736
    static bool attr_set = false;
    if (!attr_set) {
        cudaFuncSetAttribute(k_gemm_mma, cudaFuncAttributeMaxDynamicSharedMemorySize, dyn);
        attr_set = true;
    }

    k_reset<<<1, 32>>>();
    k_prep<<<NTOK / 8 + 512, 256>>>(X, pY, W_end, b_end, W_hcw, W_roo, out);
    k_gemm_mma<<<dim3(CDIM / BN, NTOK / BM, 2), 256, dyn>>>();
    k_softmax<<<dim3(NTOK / 8, 1, 2), 256>>>(Y, b_hcw, b_roo, out);
}

// round 14
// speedup vs baseline: 1.0787x; 1.0356x over previous
#include <cuda_runtime.h>
#include <cuda_bf16.h>
#include <math.h>
#include <stdint.h>

// Problem constants (B=32, S=512, H=2048, FP=SP=1024)
#define NTOK 16384
#define HDIM 2048
#define CDIM 1024
#define OUTW 2050

// GEMM tiling (mma.sync path)
#define BM 128
#define BN 128
#define BK 64                   // bf16 elems per K-stage = 128 bytes/row
#define KT (HDIM / BK)          // 32
#define SPLIT_SZ 16384          // 128 rows x 128 bytes
#define STAGE_SZ (4 * SPLIT_SZ) // Ah, Al, Bh, Bl = 64 KB
#define NSTAGE 3

// ---------------------------------------------------------------------------
// Scratch (allocation-free: __device__ globals)
// ---------------------------------------------------------------------------
__device__ float g_logits[2][(size_t)NTOK * CDIM];
__device__ __nv_bfloat16 g_Ahi[2][(size_t)NTOK * HDIM];
__device__ __nv_bfloat16 g_Alo[2][(size_t)NTOK * HDIM];
__device__ __nv_bfloat16 g_Whi[2][(size_t)CDIM * HDIM];
__device__ __nv_bfloat16 g_Wlo[2][(size_t)CDIM * HDIM];
__device__ int   g_list[2][NTOK];
__device__ int   g_cnt[2];
__device__ float g_nonend[NTOK];

// ---------------------------------------------------------------------------
// helpers
// ---------------------------------------------------------------------------
__device__ __forceinline__ uint32_t smem_u32(const void* p) {
    uint32_t a;
    asm("{ .reg .u64 t; cvta.to.shared.u64 t, %1; cvt.u32.u64 %0, t; }" : "=r"(a) : "l"(p));
    return a;
}
__device__ __forceinline__ uint32_t swz128(uint32_t o) { return o ^ ((o >> 3) & 0x70); }
__device__ __forceinline__ void cp16(uint32_t dst, const void* src) {
    asm volatile("cp.async.cg.shared.global [%0], [%1], 16;" :: "r"(dst), "l"(src));
}
__device__ __forceinline__ void cp_commit() { asm volatile("cp.async.commit_group;" ::: "memory"); }
template <int N> __device__ __forceinline__ void cp_wait() {
    asm volatile("cp.async.wait_group %0;" :: "n"(N) : "memory");
}
__device__ __forceinline__ void ldsm4(uint32_t* r, uint32_t addr) {
    asm volatile("ldmatrix.sync.aligned.m8n8.x4.shared.b16 {%0,%1,%2,%3}, [%4];"
                 : "=r"(r[0]), "=r"(r[1]), "=r"(r[2]), "=r"(r[3]) : "r"(addr));
}
__device__ __forceinline__ void hmma(float* c, const uint32_t* a, uint32_t b0, uint32_t b1) {
    asm volatile("mma.sync.aligned.m16n8k16.row.col.f32.bf16.bf16.f32 "
                 "{%0,%1,%2,%3}, {%4,%5,%6,%7}, {%8,%9}, {%0,%1,%2,%3};"
                 : "+f"(c[0]), "+f"(c[1]), "+f"(c[2]), "+f"(c[3])
                 : "r"(a[0]), "r"(a[1]), "r"(a[2]), "r"(a[3]), "r"(b0), "r"(b1));
}
__device__ __forceinline__ void split2(float a, float b, uint32_t& hi, uint32_t& lo) {
    __nv_bfloat162 h = __floats2bfloat162_rn(a, b);
    float2 hf = __bfloat1622float2(h);
    __nv_bfloat162 l = __floats2bfloat162_rn(a - hf.x, b - hf.y);
    hi = *reinterpret_cast<uint32_t*>(&h);
    lo = *reinterpret_cast<uint32_t*>(&l);
}

// ---------------------------------------------------------------------------
// Kernel 0: reset counters
// ---------------------------------------------------------------------------
__global__ void k_reset() {
    if (threadIdx.x < 2) g_cnt[threadIdx.x] = 0;
}

// ---------------------------------------------------------------------------
// Kernel 1: MERGED classify (blocks [0, 2048)) + weight split (blocks
// [2048, 2048+512)).  [R13 exact]
// ---------------------------------------------------------------------------
__global__ __launch_bounds__(256) void k_prep(
    const float* __restrict__ X, const int* __restrict__ pY,
    const float* __restrict__ W_end, const float* __restrict__ b_end,
    const float* __restrict__ W_hcw, const float* __restrict__ W_roo,
    float* __restrict__ out)
{
    const int warp = threadIdx.x >> 5;
    const int lane = threadIdx.x & 31;

    if (blockIdx.x >= NTOK / 8) {
        const int b = blockIdx.x - NTOK / 8;        // 0..511
        const int z = b >> 8;                       // 0..1
        const int half = (b & 255) * 8 + warp;      // 0 .. 2*CDIM-1
        const int rowi = half >> 1;
        const int off  = (half & 1) * 256;          // float4 offset within row
        const float* W = z ? W_roo : W_hcw;
        const float4* s = reinterpret_cast<const float4*>(W + (size_t)rowi * HDIM) + off;
        uint2* dh = reinterpret_cast<uint2*>(g_Whi[z] + (size_t)rowi * HDIM) + off;
        uint2* dl = reinterpret_cast<uint2*>(g_Wlo[z] + (size_t)rowi * HDIM) + off;
        #pragma unroll
        for (int i = 0; i < 8; ++i) {
            float4 v = s[lane + 32 * i];
            uint32_t h0, l0, h1, l1;
            split2(v.x, v.y, h0, l0);
            split2(v.z, v.w, h1, l1);
            dh[lane + 32 * i] = make_uint2(h0, h1);
            dl[lane + 32 * i] = make_uint2(l0, l1);
        }
        return;
    }

    const int t = blockIdx.x * 8 + warp;

    const float4* x4 = reinterpret_cast<const float4*>(X + (size_t)t * HDIM);
    const float4* w4 = reinterpret_cast<const float4*>(W_end);
    float s = 0.f;
    #pragma unroll
    for (int i = 0; i < 16; ++i) {
        float4 a = x4[lane + 32 * i];
        float4 b = w4[lane + 32 * i];
        s += a.x * b.x + a.y * b.y + a.z * b.z + a.w * b.w;
    }
    #pragma unroll
    for (int o = 16; o; o >>= 1) s += __shfl_xor_sync(0xffffffffu, s, o);
    const float logit = s + b_end[0];
    const float p = 1.f / (1.f + expf(-logit));

    if (lane == 0) g_nonend[t] = 1.f - p;

    const int c = pY[t];
    float* lp  = out;
    float* row = out + NTOK + (size_t)t * OUTW;

    int z0, z1, z2, z3;
    if (c == 0) {
        if (lane == 0) { lp[t] = logf(p); row[0] = p; row[1] = p; }
        z0 = 2; z1 = OUTW; z2 = 0; z3 = 0;
    } else if (c == 1 || c == 2) {
        const int z = c - 1;
        int q = 0;
        if (lane == 0) { q = atomicAdd(&g_cnt[z], 1); g_list[z][q] = t; }
        q = __shfl_sync(0xffffffffu, q, 0);
        uint2* dh = reinterpret_cast<uint2*>(g_Ahi[z] + (size_t)q * HDIM);
        uint2* dl = reinterpret_cast<uint2*>(g_Alo[z] + (size_t)q * HDIM);
        #pragma unroll
        for (int i = 0; i < 16; ++i) {
            float4 v = x4[lane + 32 * i];
            uint32_t h0, l0, h1, l1;
            split2(v.x, v.y, h0, l0);
            split2(v.z, v.w, h1, l1);
            dh[lane + 32 * i] = make_uint2(h0, h1);
            dl[lane + 32 * i] = make_uint2(l0, l1);
        }
        if (z == 0) { z0 = 0; z1 = 2; z2 = 2 + CDIM; z3 = OUTW; }
        else        { z0 = 0; z1 = 2 + CDIM; z2 = 0; z3 = 0; }
    } else {
        if (lane == 0) lp[t] = 0.f;
        z0 = 0; z1 = OUTW; z2 = 0; z3 = 0;
    }
    for (int i = z0 + lane; i < z1; i += 32) row[i] = 0.f;
    for (int i = z2 + lane; i < z3; i += 32) row[i] = 0.f;
}

// ---------------------------------------------------------------------------
// Kernel 2: split-bf16 GEMM via mma.sync.m16n8k16 (HMMA).
// R13 structure; ONLY change: per-K-iter issue order. The 16 cp.async of the
// kt+2 prefetch are now issued AFTER the s0 fragment loads and first MMA
// block, so the tensor pipe starts immediately and the LDGSTS issue cost
// (~128 cyc/warp) overlaps MMA execution instead of preceding it.
// ---------------------------------------------------------------------------
__device__ __forceinline__ void load_stage(int z, int m0, int n0, int k0,
                                           uint32_t sbase, int tid)
{
    const __nv_bfloat16* Ah = g_Ahi[z];
    const __nv_bfloat16* Al = g_Alo[z];
    const __nv_bfloat16* Bh = g_Whi[z];
    const __nv_bfloat16* Bl = g_Wlo[z];
    #pragma unroll
    for (int i = 0; i < 4; ++i) {
        int c = tid + 256 * i;
        int r = c >> 3, cc = c & 7;
        uint32_t off = swz128((uint32_t)(r * 128 + cc * 16));
        size_t ga = (size_t)(m0 + r) * HDIM + k0 + cc * 8;
        size_t gb = (size_t)(n0 + r) * HDIM + k0 + cc * 8;
        cp16(sbase + off,                Ah + ga);
        cp16(sbase + SPLIT_SZ + off,     Al + ga);
        cp16(sbase + 2 * SPLIT_SZ + off, Bh + gb);
        cp16(sbase + 3 * SPLIT_SZ + off, Bl + gb);
    }
}

__device__ __forceinline__ void load_frags(
    uint32_t Af[2][2][4], uint32_t Bf[2][4][4], uint32_t st, int kb,
    int a_row, int a_kb, int b_row, int b_kb)
{
    #pragma unroll
    for (int i = 0; i < 2; ++i) {
        uint32_t off = swz128((uint32_t)((a_row + i * 16) * 128 + kb + a_kb));
        ldsm4(Af[0][i], st + off);
        ldsm4(Af[1][i], st + SPLIT_SZ + off);
    }
    #pragma unroll
    for (int j = 0; j < 4; ++j) {
        uint32_t off = swz128((uint32_t)((b_row + j * 16) * 128 + kb + b_kb));
        ldsm4(Bf[0][j], st + 2 * SPLIT_SZ + off);
        ldsm4(Bf[1][j], st + 3 * SPLIT_SZ + off);
    }
}

__device__ __forceinline__ void mma_block(
    float acc[2][8][4], uint32_t Af[2][2][4], uint32_t Bf[2][4][4])
{
    #pragma unroll
    for (int i = 0; i < 2; ++i)
        #pragma unroll
        for (int j = 0; j < 8; ++j) {
            const uint32_t bh0 = Bf[0][j >> 1][(j & 1) * 2];
            const uint32_t bh1 = Bf[0][j >> 1][(j & 1) * 2 + 1];
            const uint32_t bl0 = Bf[1][j >> 1][(j & 1) * 2];
            const uint32_t bl1 = Bf[1][j >> 1][(j & 1) * 2 + 1];
            hmma(acc[i][j], Af[0][i], bh0, bh1);   // hi*hi
            hmma(acc[i][j], Af[0][i], bl0, bl1);   // hi*lo
            hmma(acc[i][j], Af[1][i], bh0, bh1);   // lo*hi
        }
}

__global__ __launch_bounds__(256, 1) void k_gemm_mma()
{
    extern __shared__ char dsm[];
    const int z   = blockIdx.z;
    const int cnt = g_cnt[z];
    const int m0  = blockIdx.y * BM;
    if (m0 >= cnt) return;
    const int n0  = blockIdx.x * BN;
    const int tid  = threadIdx.x;
    const int wid  = tid >> 5;
    const int lane = tid & 31;
    const int warpM = wid & 3;
    const int warpN = wid >> 2;

    uint32_t sb = (smem_u32(dsm) + 127u) & ~127u;

    float acc[2][8][4];
    #pragma unroll
    for (int i = 0; i < 2; ++i)
        #pragma unroll
        for (int j = 0; j < 8; ++j)
            #pragma unroll
            for (int q = 0; q < 4; ++q) acc[i][j][q] = 0.f;

    load_stage(z, m0, n0, 0,  sb,            tid); cp_commit();
    load_stage(z, m0, n0, BK, sb + STAGE_SZ, tid); cp_commit();

    const int sub  = lane >> 3;
    const int lrow = lane & 7;
    const int a_row = warpM * 32 + (sub & 1) * 8 + lrow;
    const int a_kb  = (sub >> 1) * 16;
    const int b_row = warpN * 64 + (sub >> 1) * 8 + lrow;
    const int b_kb  = (sub & 1) * 16;

    uint32_t Af[2][2][2][4];   // [buf][split][mtile][4]
    uint32_t Bf[2][2][4][4];   // [buf][split][ntile][4]

    for (int kt = 0; kt < KT; ++kt) {
        if (kt >= KT - 1) cp_wait<0>(); else cp_wait<1>();
        __syncthreads();
        const uint32_t st = sb + (kt % NSTAGE) * STAGE_SZ;

        // tensor pipe first: frags for s0 and s1, then MMA s0
        load_frags(Af[0], Bf[0], st, 0,  a_row, a_kb, b_row, b_kb);
        load_frags(Af[1], Bf[1], st, 32, a_row, a_kb, b_row, b_kb);
        mma_block(acc, Af[0], Bf[0]);                       // s0

        // prefetch kt+2: cp.async issue now overlaps MMA execution
        if (kt + 2 < KT) {
            load_stage(z, m0, n0, (kt + 2) * BK, sb + ((kt + 2) % NSTAGE) * STAGE_SZ, tid);
            cp_commit();
        }

        load_frags(Af[0], Bf[0], st, 64, a_row, a_kb, b_row, b_kb);   // s2 frags
        mma_block(acc, Af[1], Bf[1]);                       // s1
        load_frags(Af[1], Bf[1], st, 96, a_row, a_kb, b_row, b_kb);   // s3 frags
        mma_block(acc, Af[0], Bf[0]);                       // s2
        mma_block(acc, Af[1], Bf[1]);                       // s3
    }

    const int g = lane >> 2, tq = lane & 3;
    float* Lg = g_logits[z];
    #pragma unroll
    for (int i = 0; i < 2; ++i) {
        const int r0 = m0 + warpM * 32 + i * 16 + g;
        #pragma unroll
        for (int j = 0; j < 8; ++j) {
            const int col = n0 + warpN * 64 + j * 8 + 2 * tq;
            if (r0 < cnt)
                *reinterpret_cast<float2*>(Lg + (size_t)r0 * CDIM + col) =
                    make_float2(acc[i][j][0], acc[i][j][1]);
            if (r0 + 8 < cnt)
                *reinterpret_cast<float2*>(Lg + (size_t)(r0 + 8) * CDIM + col) =
                    make_float2(acc[i][j][2], acc[i][j][3]);
        }
    }
}

// ---------------------------------------------------------------------------
// Kernel 3: softmax + scale by non_end + scatter + log_prob.  [R13 exact]
// ---------------------------------------------------------------------------
__global__ __launch_bounds__(256) void k_softmax(
    const int* __restrict__ Y,
    const float* __restrict__ b_hcw, const float* __restrict__ b_roo,
    float* __restrict__ out)
{
    const int z    = blockIdx.z;
    const int warp = threadIdx.x >> 5;
    const int lane = threadIdx.x & 31;
    const int pos  = blockIdx.x * 8 + warp;
    if (pos >= g_cnt[z]) return;
    const int t = g_list[z][pos];

    const float* __restrict__ bias = (z == 0) ? b_hcw : b_roo;
    const float* Lrow = g_logits[z] + (size_t)pos * CDIM;
    const float4* L4 = reinterpret_cast<const float4*>(Lrow);
    const float4* B4 = reinterpret_cast<const float4*>(bias);

    float4 v[8];
    float mx = -1e30f;
    #pragma unroll
    for (int i = 0; i < 8; ++i) {
        float4 a = L4[lane + 32 * i];
        float4 b = B4[lane + 32 * i];
        a.x += b.x; a.y += b.y; a.z += b.z; a.w += b.w;
        v[i] = a;
        mx = fmaxf(mx, fmaxf(fmaxf(a.x, a.y), fmaxf(a.z, a.w)));
    }
    #pragma unroll
    for (int o = 16; o; o >>= 1) mx = fmaxf(mx, __shfl_xor_sync(0xffffffffu, mx, o));

    float sum = 0.f;
    #pragma unroll
    for (int i = 0; i < 8; ++i) {
        v[i].x = expf(v[i].x - mx); v[i].y = expf(v[i].y - mx);
        v[i].z = expf(v[i].z - mx); v[i].w = expf(v[i].w - mx);
        sum += (v[i].x + v[i].y) + (v[i].z + v[i].w);
    }
    #pragma unroll
    for (int o = 16; o; o >>= 1) sum += __shfl_xor_sync(0xffffffffu, sum, o);

    const float ne = g_nonend[t];
    const float scale = ne / sum;

    float* row = out + NTOK + (size_t)t * OUTW + ((z == 0) ? 2 : 2 + CDIM);
    #pragma unroll
    for (int i = 0; i < 8; ++i) {
        const int c0 = 4 * (lane + 32 * i);
        *reinterpret_cast<float2*>(row + c0)     = make_float2(v[i].x * scale, v[i].y * scale);
        *reinterpret_cast<float2*>(row + c0 + 2) = make_float2(v[i].z * scale, v[i].w * scale);
    }

    if (lane == 0) {
        const int yv = Y[t];
        int idx = yv - 2 - ((z == 0) ? 0 : CDIM);
        idx = min(max(idx, 0), CDIM - 1);
        const float li = Lrow[idx] + bias[idx];
        out[t] = (li - mx) - logf(sum) + logf(ne);
    }
}

// ---------------------------------------------------------------------------
// Launcher
// ---------------------------------------------------------------------------
extern "C" void kernel_launch(void* const* d_in, const int* in_sizes, int n_in,
                              void* d_out, int out_size)
{
    const float* X     = (const float*)d_in[0];
    const int*   pY    = (const int*)d_in[1];
    const int*   Y     = (const int*)d_in[2];
    const float* W_end = (const float*)d_in[3];
    const float* b_end = (const float*)d_in[4];
    const float* W_hcw = (const float*)d_in[5];
    const float* b_hcw = (const float*)d_in[6];
    const float* W_roo = (const float*)d_in[7];
    const float* b_roo = (const float*)d_in[8];
    float* out = (float*)d_out;
    (void)in_sizes; (void)n_in; (void)out_size;

    const int dyn = 128 + NSTAGE * STAGE_SZ;   // 196736
    static bool attr_set = false;
    if (!attr_set) {
        cudaFuncSetAttribute(k_gemm_mma, cudaFuncAttributeMaxDynamicSharedMemorySize, dyn);
        attr_set = true;
    }

    k_reset<<<1, 32>>>();
    k_prep<<<NTOK / 8 + 512, 256>>>(X, pY, W_end, b_end, W_hcw, W_roo, out);
    k_gemm_mma<<<dim3(CDIM / BN, NTOK / BM, 2), 256, dyn>>>();
    k_softmax<<<dim3(NTOK / 8, 1, 2), 256>>>(Y, b_hcw, b_roo, out);
}

// round 15
// speedup vs baseline: 1.0824x; 1.0034x over previous
#include <cuda_runtime.h>
#include <cuda_bf16.h>
#include <math.h>
#include <stdint.h>

// Problem constants (B=32, S=512, H=2048, FP=SP=1024)
#define NTOK 16384
#define HDIM 2048
#define CDIM 1024
#define OUTW 2050

// GEMM tiling (mma.sync path)
#define BM 128
#define BN 128
#define BK 64                   // bf16 elems per K-stage = 128 bytes/row
#define KT (HDIM / BK)          // 32
#define SPLIT_SZ 16384          // 128 rows x 128 bytes
#define STAGE_SZ (4 * SPLIT_SZ) // Ah, Al, Bh, Bl = 64 KB
#define NSTAGE 3

// ---------------------------------------------------------------------------
// Scratch (allocation-free: __device__ globals)
// ---------------------------------------------------------------------------
__device__ float g_logits[2][(size_t)NTOK * CDIM];
__device__ __nv_bfloat16 g_Ahi[2][(size_t)NTOK * HDIM];
__device__ __nv_bfloat16 g_Alo[2][(size_t)NTOK * HDIM];
__device__ __nv_bfloat16 g_Whi[2][(size_t)CDIM * HDIM];
__device__ __nv_bfloat16 g_Wlo[2][(size_t)CDIM * HDIM];
__device__ int   g_list[2][NTOK];
__device__ int   g_cnt[2];
__device__ float g_nonend[NTOK];

// ---------------------------------------------------------------------------
// helpers
// ---------------------------------------------------------------------------
__device__ __forceinline__ uint32_t smem_u32(const void* p) {
    uint32_t a;
    asm("{ .reg .u64 t; cvta.to.shared.u64 t, %1; cvt.u32.u64 %0, t; }" : "=r"(a) : "l"(p));
    return a;
}
__device__ __forceinline__ uint32_t swz128(uint32_t o) { return o ^ ((o >> 3) & 0x70); }
__device__ __forceinline__ void cp16(uint32_t dst, const void* src) {
    asm volatile("cp.async.cg.shared.global [%0], [%1], 16;" :: "r"(dst), "l"(src));
}
__device__ __forceinline__ void cp_commit() { asm volatile("cp.async.commit_group;" ::: "memory"); }
template <int N> __device__ __forceinline__ void cp_wait() {
    asm volatile("cp.async.wait_group %0;" :: "n"(N) : "memory");
}
__device__ __forceinline__ void ldsm4(uint32_t* r, uint32_t addr) {
    asm volatile("ldmatrix.sync.aligned.m8n8.x4.shared.b16 {%0,%1,%2,%3}, [%4];"
                 : "=r"(r[0]), "=r"(r[1]), "=r"(r[2]), "=r"(r[3]) : "r"(addr));
}
__device__ __forceinline__ void hmma(float* c, const uint32_t* a, uint32_t b0, uint32_t b1) {
    asm volatile("mma.sync.aligned.m16n8k16.row.col.f32.bf16.bf16.f32 "
                 "{%0,%1,%2,%3}, {%4,%5,%6,%7}, {%8,%9}, {%0,%1,%2,%3};"
                 : "+f"(c[0]), "+f"(c[1]), "+f"(c[2]), "+f"(c[3])
                 : "r"(a[0]), "r"(a[1]), "r"(a[2]), "r"(a[3]), "r"(b0), "r"(b1));
}
__device__ __forceinline__ void split2(float a, float b, uint32_t& hi, uint32_t& lo) {
    __nv_bfloat162 h = __floats2bfloat162_rn(a, b);
    float2 hf = __bfloat1622float2(h);
    __nv_bfloat162 l = __floats2bfloat162_rn(a - hf.x, b - hf.y);
    hi = *reinterpret_cast<uint32_t*>(&h);
    lo = *reinterpret_cast<uint32_t*>(&l);
}

// ---------------------------------------------------------------------------
// Kernel 0: reset counters
// ---------------------------------------------------------------------------
__global__ void k_reset() {
    if (threadIdx.x < 2) g_cnt[threadIdx.x] = 0;
}

// ---------------------------------------------------------------------------
// Kernel 1: MERGED classify (blocks [0, 2048)) + weight split (blocks
// [2048, 2048+512)).  [R13 exact]
// ---------------------------------------------------------------------------
__global__ __launch_bounds__(256) void k_prep(
    const float* __restrict__ X, const int* __restrict__ pY,
    const float* __restrict__ W_end, const float* __restrict__ b_end,
    const float* __restrict__ W_hcw, const float* __restrict__ W_roo,
    float* __restrict__ out)
{
    const int warp = threadIdx.x >> 5;
    const int lane = threadIdx.x & 31;

    if (blockIdx.x >= NTOK / 8) {
        const int b = blockIdx.x - NTOK / 8;        // 0..511
        const int z = b >> 8;                       // 0..1
        const int half = (b & 255) * 8 + warp;      // 0 .. 2*CDIM-1
        const int rowi = half >> 1;
        const int off  = (half & 1) * 256;          // float4 offset within row
        const float* W = z ? W_roo : W_hcw;
        const float4* s = reinterpret_cast<const float4*>(W + (size_t)rowi * HDIM) + off;
        uint2* dh = reinterpret_cast<uint2*>(g_Whi[z] + (size_t)rowi * HDIM) + off;
        uint2* dl = reinterpret_cast<uint2*>(g_Wlo[z] + (size_t)rowi * HDIM) + off;
        #pragma unroll
        for (int i = 0; i < 8; ++i) {
            float4 v = s[lane + 32 * i];
            uint32_t h0, l0, h1, l1;
            split2(v.x, v.y, h0, l0);
            split2(v.z, v.w, h1, l1);
            dh[lane + 32 * i] = make_uint2(h0, h1);
            dl[lane + 32 * i] = make_uint2(l0, l1);
        }
        return;
    }

    const int t = blockIdx.x * 8 + warp;

    const float4* x4 = reinterpret_cast<const float4*>(X + (size_t)t * HDIM);
    const float4* w4 = reinterpret_cast<const float4*>(W_end);
    float s = 0.f;
    #pragma unroll
    for (int i = 0; i < 16; ++i) {
        float4 a = x4[lane + 32 * i];
        float4 b = w4[lane + 32 * i];
        s += a.x * b.x + a.y * b.y + a.z * b.z + a.w * b.w;
    }
    #pragma unroll
    for (int o = 16; o; o >>= 1) s += __shfl_xor_sync(0xffffffffu, s, o);
    const float logit = s + b_end[0];
    const float p = 1.f / (1.f + expf(-logit));

    if (lane == 0) g_nonend[t] = 1.f - p;

    const int c = pY[t];
    float* lp  = out;
    float* row = out + NTOK + (size_t)t * OUTW;

    int z0, z1, z2, z3;
    if (c == 0) {
        if (lane == 0) { lp[t] = logf(p); row[0] = p; row[1] = p; }
        z0 = 2; z1 = OUTW; z2 = 0; z3 = 0;
    } else if (c == 1 || c == 2) {
        const int z = c - 1;
        int q = 0;
        if (lane == 0) { q = atomicAdd(&g_cnt[z], 1); g_list[z][q] = t; }
        q = __shfl_sync(0xffffffffu, q, 0);
        uint2* dh = reinterpret_cast<uint2*>(g_Ahi[z] + (size_t)q * HDIM);
        uint2* dl = reinterpret_cast<uint2*>(g_Alo[z] + (size_t)q * HDIM);
        #pragma unroll
        for (int i = 0; i < 16; ++i) {
            float4 v = x4[lane + 32 * i];
            uint32_t h0, l0, h1, l1;
            split2(v.x, v.y, h0, l0);
            split2(v.z, v.w, h1, l1);
            dh[lane + 32 * i] = make_uint2(h0, h1);
            dl[lane + 32 * i] = make_uint2(l0, l1);
        }
        if (z == 0) { z0 = 0; z1 = 2; z2 = 2 + CDIM; z3 = OUTW; }
        else        { z0 = 0; z1 = 2 + CDIM; z2 = 0; z3 = 0; }
    } else {
        if (lane == 0) lp[t] = 0.f;
        z0 = 0; z1 = OUTW; z2 = 0; z3 = 0;
    }
    for (int i = z0 + lane; i < z1; i += 32) row[i] = 0.f;
    for (int i = z2 + lane; i < z3; i += 32) row[i] = 0.f;
}

// ---------------------------------------------------------------------------
// Kernel 2: split-bf16 GEMM via mma.sync.m16n8k16 (HMMA).
// R14 structure; ONLY change: the kt+2 prefetch is split into 4 chunks of
// 4 cp.async, one chunk issued after each MMA block, so LDGSTS issue cost
// is evenly diluted across the iteration instead of bursting.
// ---------------------------------------------------------------------------
__device__ __forceinline__ void load_chunk(int z, int m0, int n0, int k0,
                                           uint32_t sbase, int tid, int i)
{
    const __nv_bfloat16* Ah = g_Ahi[z];
    const __nv_bfloat16* Al = g_Alo[z];
    const __nv_bfloat16* Bh = g_Whi[z];
    const __nv_bfloat16* Bl = g_Wlo[z];
    int c = tid + 256 * i;
    int r = c >> 3, cc = c & 7;
    uint32_t off = swz128((uint32_t)(r * 128 + cc * 16));
    size_t ga = (size_t)(m0 + r) * HDIM + k0 + cc * 8;
    size_t gb = (size_t)(n0 + r) * HDIM + k0 + cc * 8;
    cp16(sbase + off,                Ah + ga);
    cp16(sbase + SPLIT_SZ + off,     Al + ga);
    cp16(sbase + 2 * SPLIT_SZ + off, Bh + gb);
    cp16(sbase + 3 * SPLIT_SZ + off, Bl + gb);
}

__device__ __forceinline__ void load_stage(int z, int m0, int n0, int k0,
                                           uint32_t sbase, int tid)
{
    #pragma unroll
    for (int i = 0; i < 4; ++i) load_chunk(z, m0, n0, k0, sbase, tid, i);
}

__device__ __forceinline__ void load_frags(
    uint32_t Af[2][2][4], uint32_t Bf[2][4][4], uint32_t st, int kb,
    int a_row, int a_kb, int b_row, int b_kb)
{
    #pragma unroll
    for (int i = 0; i < 2; ++i) {
        uint32_t off = swz128((uint32_t)((a_row + i * 16) * 128 + kb + a_kb));
        ldsm4(Af[0][i], st + off);
        ldsm4(Af[1][i], st + SPLIT_SZ + off);
    }
    #pragma unroll
    for (int j = 0; j < 4; ++j) {
        uint32_t off = swz128((uint32_t)((b_row + j * 16) * 128 + kb + b_kb));
        ldsm4(Bf[0][j], st + 2 * SPLIT_SZ + off);
        ldsm4(Bf[1][j], st + 3 * SPLIT_SZ + off);
    }
}

__device__ __forceinline__ void mma_block(
    float acc[2][8][4], uint32_t Af[2][2][4], uint32_t Bf[2][4][4])
{
    #pragma unroll
    for (int i = 0; i < 2; ++i)
        #pragma unroll
        for (int j = 0; j < 8; ++j) {
            const uint32_t bh0 = Bf[0][j >> 1][(j & 1) * 2];
            const uint32_t bh1 = Bf[0][j >> 1][(j & 1) * 2 + 1];
            const uint32_t bl0 = Bf[1][j >> 1][(j & 1) * 2];
            const uint32_t bl1 = Bf[1][j >> 1][(j & 1) * 2 + 1];
            hmma(acc[i][j], Af[0][i], bh0, bh1);   // hi*hi
            hmma(acc[i][j], Af[0][i], bl0, bl1);   // hi*lo
            hmma(acc[i][j], Af[1][i], bh0, bh1);   // lo*hi
        }
}

__global__ __launch_bounds__(256, 1) void k_gemm_mma()
{
    extern __shared__ char dsm[];
    const int z   = blockIdx.z;
    const int cnt = g_cnt[z];
    const int m0  = blockIdx.y * BM;
    if (m0 >= cnt) return;
    const int n0  = blockIdx.x * BN;
    const int tid  = threadIdx.x;
    const int wid  = tid >> 5;
    const int lane = tid & 31;
    const int warpM = wid & 3;
    const int warpN = wid >> 2;

    uint32_t sb = (smem_u32(dsm) + 127u) & ~127u;

    float acc[2][8][4];
    #pragma unroll
    for (int i = 0; i < 2; ++i)
        #pragma unroll
        for (int j = 0; j < 8; ++j)
            #pragma unroll
            for (int q = 0; q < 4; ++q) acc[i][j][q] = 0.f;

    load_stage(z, m0, n0, 0,  sb,            tid); cp_commit();
    load_stage(z, m0, n0, BK, sb + STAGE_SZ, tid); cp_commit();

    const int sub  = lane >> 3;
    const int lrow = lane & 7;
    const int a_row = warpM * 32 + (sub & 1) * 8 + lrow;
    const int a_kb  = (sub >> 1) * 16;
    const int b_row = warpN * 64 + (sub >> 1) * 8 + lrow;
    const int b_kb  = (sub & 1) * 16;

    uint32_t Af[2][2][2][4];   // [buf][split][mtile][4]
    uint32_t Bf[2][2][4][4];   // [buf][split][ntile][4]

    for (int kt = 0; kt < KT; ++kt) {
        if (kt >= KT - 1) cp_wait<0>(); else cp_wait<1>();
        __syncthreads();
        const uint32_t st = sb + (kt % NSTAGE) * STAGE_SZ;
        const bool pf = (kt + 2 < KT);
        const int pk = (kt + 2) * BK;
        const uint32_t ps = sb + ((kt + 2) % NSTAGE) * STAGE_SZ;

        // tensor pipe first: frags for s0 and s1, then MMA s0
        load_frags(Af[0], Bf[0], st, 0,  a_row, a_kb, b_row, b_kb);
        load_frags(Af[1], Bf[1], st, 32, a_row, a_kb, b_row, b_kb);
        mma_block(acc, Af[0], Bf[0]);                       // s0
        if (pf) load_chunk(z, m0, n0, pk, ps, tid, 0);

        load_frags(Af[0], Bf[0], st, 64, a_row, a_kb, b_row, b_kb);   // s2 frags
        mma_block(acc, Af[1], Bf[1]);                       // s1
        if (pf) load_chunk(z, m0, n0, pk, ps, tid, 1);

        load_frags(Af[1], Bf[1], st, 96, a_row, a_kb, b_row, b_kb);   // s3 frags
        mma_block(acc, Af[0], Bf[0]);                       // s2
        if (pf) load_chunk(z, m0, n0, pk, ps, tid, 2);

        mma_block(acc, Af[1], Bf[1]);                       // s3
        if (pf) { load_chunk(z, m0, n0, pk, ps, tid, 3); cp_commit(); }
    }

    const int g = lane >> 2, tq = lane & 3;
    float* Lg = g_logits[z];
    #pragma unroll
    for (int i = 0; i < 2; ++i) {
        const int r0 = m0 + warpM * 32 + i * 16 + g;
        #pragma unroll
        for (int j = 0; j < 8; ++j) {
            const int col = n0 + warpN * 64 + j * 8 + 2 * tq;
            if (r0 < cnt)
                *reinterpret_cast<float2*>(Lg + (size_t)r0 * CDIM + col) =
                    make_float2(acc[i][j][0], acc[i][j][1]);
            if (r0 + 8 < cnt)
                *reinterpret_cast<float2*>(Lg + (size_t)(r0 + 8) * CDIM + col) =
                    make_float2(acc[i][j][2], acc[i][j][3]);
        }
    }
}

// ---------------------------------------------------------------------------
// Kernel 3: softmax + scale by non_end + scatter + log_prob.  [R13 exact]
// ---------------------------------------------------------------------------
__global__ __launch_bounds__(256) void k_softmax(
    const int* __restrict__ Y,
    const float* __restrict__ b_hcw, const float* __restrict__ b_roo,
    float* __restrict__ out)
{
    const int z    = blockIdx.z;
    const int warp = threadIdx.x >> 5;
    const int lane = threadIdx.x & 31;
    const int pos  = blockIdx.x * 8 + warp;
    if (pos >= g_cnt[z]) return;
    const int t = g_list[z][pos];

    const float* __restrict__ bias = (z == 0) ? b_hcw : b_roo;
    const float* Lrow = g_logits[z] + (size_t)pos * CDIM;
    const float4* L4 = reinterpret_cast<const float4*>(Lrow);
    const float4* B4 = reinterpret_cast<const float4*>(bias);

    float4 v[8];
    float mx = -1e30f;
    #pragma unroll
    for (int i = 0; i < 8; ++i) {
        float4 a = L4[lane + 32 * i];
        float4 b = B4[lane + 32 * i];
        a.x += b.x; a.y += b.y; a.z += b.z; a.w += b.w;
        v[i] = a;
        mx = fmaxf(mx, fmaxf(fmaxf(a.x, a.y), fmaxf(a.z, a.w)));
    }
    #pragma unroll
    for (int o = 16; o; o >>= 1) mx = fmaxf(mx, __shfl_xor_sync(0xffffffffu, mx, o));

    float sum = 0.f;
    #pragma unroll
    for (int i = 0; i < 8; ++i) {
        v[i].x = expf(v[i].x - mx); v[i].y = expf(v[i].y - mx);
        v[i].z = expf(v[i].z - mx); v[i].w = expf(v[i].w - mx);
        sum += (v[i].x + v[i].y) + (v[i].z + v[i].w);
    }
    #pragma unroll
    for (int o = 16; o; o >>= 1) sum += __shfl_xor_sync(0xffffffffu, sum, o);

    const float ne = g_nonend[t];
    const float scale = ne / sum;

    float* row = out + NTOK + (size_t)t * OUTW + ((z == 0) ? 2 : 2 + CDIM);
    #pragma unroll
    for (int i = 0; i < 8; ++i) {
        const int c0 = 4 * (lane + 32 * i);
        *reinterpret_cast<float2*>(row + c0)     = make_float2(v[i].x * scale, v[i].y * scale);
        *reinterpret_cast<float2*>(row + c0 + 2) = make_float2(v[i].z * scale, v[i].w * scale);
    }

    if (lane == 0) {
        const int yv = Y[t];
        int idx = yv - 2 - ((z == 0) ? 0 : CDIM);
        idx = min(max(idx, 0), CDIM - 1);
        const float li = Lrow[idx] + bias[idx];
        out[t] = (li - mx) - logf(sum) + logf(ne);
    }
}

// ---------------------------------------------------------------------------
// Launcher
// ---------------------------------------------------------------------------
extern "C" void kernel_launch(void* const* d_in, const int* in_sizes, int n_in,
                              void* d_out, int out_size)
{
    const float* X     = (const float*)d_in[0];
    const int*   pY    = (const int*)d_in[1];
    const int*   Y     = (const int*)d_in[2];
    const float* W_end = (const float*)d_in[3];
    const float* b_end = (const float*)d_in[4];
    const float* W_hcw = (const float*)d_in[5];
    const float* b_hcw = (const float*)d_in[6];
    const float* W_roo = (const float*)d_in[7];
    const float* b_roo = (const float*)d_in[8];
    float* out = (float*)d_out;
    (void)in_sizes; (void)n_in; (void)out_size;

    const int dyn = 128 + NSTAGE * STAGE_SZ;   // 196736
    static bool attr_set = false;
    if (!attr_set) {
        cudaFuncSetAttribute(k_gemm_mma, cudaFuncAttributeMaxDynamicSharedMemorySize, dyn);
        attr_set = true;
    }

    k_reset<<<1, 32>>>();
    k_prep<<<NTOK / 8 + 512, 256>>>(X, pY, W_end, b_end, W_hcw, W_roo, out);
    k_gemm_mma<<<dim3(CDIM / BN, NTOK / BM, 2), 256, dyn>>>();
    k_softmax<<<dim3(NTOK / 8, 1, 2), 256>>>(Y, b_hcw, b_roo, out);
}

// round 16
// speedup vs baseline: 1.0829x; 1.0005x over previous
#include <cuda_runtime.h>
#include <cuda_bf16.h>
#include <math.h>
#include <stdint.h>

// Problem constants (B=32, S=512, H=2048, FP=SP=1024)
#define NTOK 16384
#define HDIM 2048
#define CDIM 1024
#define OUTW 2050

// GEMM tiling (mma.sync path)
#define BM 128
#define BN 128
#define BK 64                   // bf16 elems per K-stage = 128 bytes/row
#define KT (HDIM / BK)          // 32
#define SPLIT_SZ 16384          // 128 rows x 128 bytes
#define STAGE_SZ (4 * SPLIT_SZ) // Ah, Al, Bh, Bl = 64 KB
#define NSTAGE 3

// ---------------------------------------------------------------------------
// Scratch (allocation-free: __device__ globals)
// ---------------------------------------------------------------------------
__device__ float g_logits[2][(size_t)NTOK * CDIM];
__device__ __nv_bfloat16 g_Ahi[2][(size_t)NTOK * HDIM];
__device__ __nv_bfloat16 g_Alo[2][(size_t)NTOK * HDIM];
__device__ __nv_bfloat16 g_Whi[2][(size_t)CDIM * HDIM];
__device__ __nv_bfloat16 g_Wlo[2][(size_t)CDIM * HDIM];
__device__ int   g_list[2][NTOK];
__device__ int   g_cnt[2];
__device__ float g_nonend[NTOK];

// ---------------------------------------------------------------------------
// helpers
// ---------------------------------------------------------------------------
__device__ __forceinline__ uint32_t smem_u32(const void* p) {
    uint32_t a;
    asm("{ .reg .u64 t; cvta.to.shared.u64 t, %1; cvt.u32.u64 %0, t; }" : "=r"(a) : "l"(p));
    return a;
}
__device__ __forceinline__ uint32_t swz128(uint32_t o) { return o ^ ((o >> 3) & 0x70); }
__device__ __forceinline__ void cp16(uint32_t dst, const void* src) {
    asm volatile("cp.async.cg.shared.global [%0], [%1], 16;" :: "r"(dst), "l"(src));
}
__device__ __forceinline__ void cp_commit() { asm volatile("cp.async.commit_group;" ::: "memory"); }
template <int N> __device__ __forceinline__ void cp_wait() {
    asm volatile("cp.async.wait_group %0;" :: "n"(N) : "memory");
}
__device__ __forceinline__ void ldsm4(uint32_t* r, uint32_t addr) {
    asm volatile("ldmatrix.sync.aligned.m8n8.x4.shared.b16 {%0,%1,%2,%3}, [%4];"
                 : "=r"(r[0]), "=r"(r[1]), "=r"(r[2]), "=r"(r[3]) : "r"(addr));
}
__device__ __forceinline__ void hmma(float* c, const uint32_t* a, uint32_t b0, uint32_t b1) {
    asm volatile("mma.sync.aligned.m16n8k16.row.col.f32.bf16.bf16.f32 "
                 "{%0,%1,%2,%3}, {%4,%5,%6,%7}, {%8,%9}, {%0,%1,%2,%3};"
                 : "+f"(c[0]), "+f"(c[1]), "+f"(c[2]), "+f"(c[3])
                 : "r"(a[0]), "r"(a[1]), "r"(a[2]), "r"(a[3]), "r"(b0), "r"(b1));
}
__device__ __forceinline__ void split2(float a, float b, uint32_t& hi, uint32_t& lo) {
    __nv_bfloat162 h = __floats2bfloat162_rn(a, b);
    float2 hf = __bfloat1622float2(h);
    __nv_bfloat162 l = __floats2bfloat162_rn(a - hf.x, b - hf.y);
    hi = *reinterpret_cast<uint32_t*>(&h);
    lo = *reinterpret_cast<uint32_t*>(&l);
}

// ---------------------------------------------------------------------------
// Kernel 0: reset counters
// ---------------------------------------------------------------------------
__global__ void k_reset() {
    if (threadIdx.x < 2) g_cnt[threadIdx.x] = 0;
}

// ---------------------------------------------------------------------------
// Kernel 1: MERGED classify (blocks [0, 2048)) + weight split (blocks
// [2048, 2048+512)).  [R13 exact]
// ---------------------------------------------------------------------------
__global__ __launch_bounds__(256) void k_prep(
    const float* __restrict__ X, const int* __restrict__ pY,
    const float* __restrict__ W_end, const float* __restrict__ b_end,
    const float* __restrict__ W_hcw, const float* __restrict__ W_roo,
    float* __restrict__ out)
{
    const int warp = threadIdx.x >> 5;
    const int lane = threadIdx.x & 31;

    if (blockIdx.x >= NTOK / 8) {
        const int b = blockIdx.x - NTOK / 8;        // 0..511
        const int z = b >> 8;                       // 0..1
        const int half = (b & 255) * 8 + warp;      // 0 .. 2*CDIM-1
        const int rowi = half >> 1;
        const int off  = (half & 1) * 256;          // float4 offset within row
        const float* W = z ? W_roo : W_hcw;
        const float4* s = reinterpret_cast<const float4*>(W + (size_t)rowi * HDIM) + off;
        uint2* dh = reinterpret_cast<uint2*>(g_Whi[z] + (size_t)rowi * HDIM) + off;
        uint2* dl = reinterpret_cast<uint2*>(g_Wlo[z] + (size_t)rowi * HDIM) + off;
        #pragma unroll
        for (int i = 0; i < 8; ++i) {
            float4 v = s[lane + 32 * i];
            uint32_t h0, l0, h1, l1;
            split2(v.x, v.y, h0, l0);
            split2(v.z, v.w, h1, l1);
            dh[lane + 32 * i] = make_uint2(h0, h1);
            dl[lane + 32 * i] = make_uint2(l0, l1);
        }
        return;
    }

    const int t = blockIdx.x * 8 + warp;

    const float4* x4 = reinterpret_cast<const float4*>(X + (size_t)t * HDIM);
    const float4* w4 = reinterpret_cast<const float4*>(W_end);
    float s = 0.f;
    #pragma unroll
    for (int i = 0; i < 16; ++i) {
        float4 a = x4[lane + 32 * i];
        float4 b = w4[lane + 32 * i];
        s += a.x * b.x + a.y * b.y + a.z * b.z + a.w * b.w;
    }
    #pragma unroll
    for (int o = 16; o; o >>= 1) s += __shfl_xor_sync(0xffffffffu, s, o);
    const float logit = s + b_end[0];
    const float p = 1.f / (1.f + expf(-logit));

    if (lane == 0) g_nonend[t] = 1.f - p;

    const int c = pY[t];
    float* lp  = out;
    float* row = out + NTOK + (size_t)t * OUTW;

    int z0, z1, z2, z3;
    if (c == 0) {
        if (lane == 0) { lp[t] = logf(p); row[0] = p; row[1] = p; }
        z0 = 2; z1 = OUTW; z2 = 0; z3 = 0;
    } else if (c == 1 || c == 2) {
        const int z = c - 1;
        int q = 0;
        if (lane == 0) { q = atomicAdd(&g_cnt[z], 1); g_list[z][q] = t; }
        q = __shfl_sync(0xffffffffu, q, 0);
        uint2* dh = reinterpret_cast<uint2*>(g_Ahi[z] + (size_t)q * HDIM);
        uint2* dl = reinterpret_cast<uint2*>(g_Alo[z] + (size_t)q * HDIM);
        #pragma unroll
        for (int i = 0; i < 16; ++i) {
            float4 v = x4[lane + 32 * i];
            uint32_t h0, l0, h1, l1;
            split2(v.x, v.y, h0, l0);
            split2(v.z, v.w, h1, l1);
            dh[lane + 32 * i] = make_uint2(h0, h1);
            dl[lane + 32 * i] = make_uint2(l0, l1);
        }
        if (z == 0) { z0 = 0; z1 = 2; z2 = 2 + CDIM; z3 = OUTW; }
        else        { z0 = 0; z1 = 2 + CDIM; z2 = 0; z3 = 0; }
    } else {
        if (lane == 0) lp[t] = 0.f;
        z0 = 0; z1 = OUTW; z2 = 0; z3 = 0;
    }
    for (int i = z0 + lane; i < z1; i += 32) row[i] = 0.f;
    for (int i = z2 + lane; i < z3; i += 32) row[i] = 0.f;
}

// ---------------------------------------------------------------------------
// Kernel 2: split-bf16 GEMM via mma.sync.m16n8k16 (HMMA).
// R15 structure; ONLY change: strict just-in-time fragment loading. After the
// barrier only s0's 12 LDSM precede the first MMA block (was 24); each later
// frag load is issued immediately after the MMA block that frees its buffer.
// ---------------------------------------------------------------------------
__device__ __forceinline__ void load_chunk(int z, int m0, int n0, int k0,
                                           uint32_t sbase, int tid, int i)
{
    const __nv_bfloat16* Ah = g_Ahi[z];
    const __nv_bfloat16* Al = g_Alo[z];
    const __nv_bfloat16* Bh = g_Whi[z];
    const __nv_bfloat16* Bl = g_Wlo[z];
    int c = tid + 256 * i;
    int r = c >> 3, cc = c & 7;
    uint32_t off = swz128((uint32_t)(r * 128 + cc * 16));
    size_t ga = (size_t)(m0 + r) * HDIM + k0 + cc * 8;
    size_t gb = (size_t)(n0 + r) * HDIM + k0 + cc * 8;
    cp16(sbase + off,                Ah + ga);
    cp16(sbase + SPLIT_SZ + off,     Al + ga);
    cp16(sbase + 2 * SPLIT_SZ + off, Bh + gb);
    cp16(sbase + 3 * SPLIT_SZ + off, Bl + gb);
}

__device__ __forceinline__ void load_stage(int z, int m0, int n0, int k0,
                                           uint32_t sbase, int tid)
{
    #pragma unroll
    for (int i = 0; i < 4; ++i) load_chunk(z, m0, n0, k0, sbase, tid, i);
}

__device__ __forceinline__ void load_frags(
    uint32_t Af[2][2][4], uint32_t Bf[2][4][4], uint32_t st, int kb,
    int a_row, int a_kb, int b_row, int b_kb)
{
    #pragma unroll
    for (int i = 0; i < 2; ++i) {
        uint32_t off = swz128((uint32_t)((a_row + i * 16) * 128 + kb + a_kb));
        ldsm4(Af[0][i], st + off);
        ldsm4(Af[1][i], st + SPLIT_SZ + off);
    }
    #pragma unroll
    for (int j = 0; j < 4; ++j) {
        uint32_t off = swz128((uint32_t)((b_row + j * 16) * 128 + kb + b_kb));
        ldsm4(Bf[0][j], st + 2 * SPLIT_SZ + off);
        ldsm4(Bf[1][j], st + 3 * SPLIT_SZ + off);
    }
}

__device__ __forceinline__ void mma_block(
    float acc[2][8][4], uint32_t Af[2][2][4], uint32_t Bf[2][4][4])
{
    #pragma unroll
    for (int i = 0; i < 2; ++i)
        #pragma unroll
        for (int j = 0; j < 8; ++j) {
            const uint32_t bh0 = Bf[0][j >> 1][(j & 1) * 2];
            const uint32_t bh1 = Bf[0][j >> 1][(j & 1) * 2 + 1];
            const uint32_t bl0 = Bf[1][j >> 1][(j & 1) * 2];
            const uint32_t bl1 = Bf[1][j >> 1][(j & 1) * 2 + 1];
            hmma(acc[i][j], Af[0][i], bh0, bh1);   // hi*hi
            hmma(acc[i][j], Af[0][i], bl0, bl1);   // hi*lo
            hmma(acc[i][j], Af[1][i], bh0, bh1);   // lo*hi
        }
}

__global__ __launch_bounds__(256, 1) void k_gemm_mma()
{
    extern __shared__ char dsm[];
    const int z   = blockIdx.z;
    const int cnt = g_cnt[z];
    const int m0  = blockIdx.y * BM;
    if (m0 >= cnt) return;
    const int n0  = blockIdx.x * BN;
    const int tid  = threadIdx.x;
    const int wid  = tid >> 5;
    const int lane = tid & 31;
    const int warpM = wid & 3;
    const int warpN = wid >> 2;

    uint32_t sb = (smem_u32(dsm) + 127u) & ~127u;

    float acc[2][8][4];
    #pragma unroll
    for (int i = 0; i < 2; ++i)
        #pragma unroll
        for (int j = 0; j < 8; ++j)
            #pragma unroll
            for (int q = 0; q < 4; ++q) acc[i][j][q] = 0.f;

    load_stage(z, m0, n0, 0,  sb,            tid); cp_commit();
    load_stage(z, m0, n0, BK, sb + STAGE_SZ, tid); cp_commit();

    const int sub  = lane >> 3;
    const int lrow = lane & 7;
    const int a_row = warpM * 32 + (sub & 1) * 8 + lrow;
    const int a_kb  = (sub >> 1) * 16;
    const int b_row = warpN * 64 + (sub >> 1) * 8 + lrow;
    const int b_kb  = (sub & 1) * 16;

    uint32_t Af[2][2][2][4];   // [buf][split][mtile][4]
    uint32_t Bf[2][2][4][4];   // [buf][split][ntile][4]

    for (int kt = 0; kt < KT; ++kt) {
        if (kt >= KT - 1) cp_wait<0>(); else cp_wait<1>();
        __syncthreads();
        const uint32_t st = sb + (kt % NSTAGE) * STAGE_SZ;
        const bool pf = (kt + 2 < KT);
        const int pk = (kt + 2) * BK;
        const uint32_t ps = sb + ((kt + 2) % NSTAGE) * STAGE_SZ;

        // strict JIT: only s0's frags precede the first MMA block
        load_frags(Af[0], Bf[0], st, 0,  a_row, a_kb, b_row, b_kb);
        mma_block(acc, Af[0], Bf[0]);                       // s0
        load_frags(Af[1], Bf[1], st, 32, a_row, a_kb, b_row, b_kb);   // s1 frags
        if (pf) load_chunk(z, m0, n0, pk, ps, tid, 0);

        mma_block(acc, Af[1], Bf[1]);                       // s1
        load_frags(Af[0], Bf[0], st, 64, a_row, a_kb, b_row, b_kb);   // s2 frags
        if (pf) load_chunk(z, m0, n0, pk, ps, tid, 1);

        mma_block(acc, Af[0], Bf[0]);                       // s2
        load_frags(Af[1], Bf[1], st, 96, a_row, a_kb, b_row, b_kb);   // s3 frags
        if (pf) load_chunk(z, m0, n0, pk, ps, tid, 2);

        mma_block(acc, Af[1], Bf[1]);                       // s3
        if (pf) { load_chunk(z, m0, n0, pk, ps, tid, 3); cp_commit(); }
    }

    const int g = lane >> 2, tq = lane & 3;
    float* Lg = g_logits[z];
    #pragma unroll
    for (int i = 0; i < 2; ++i) {
        const int r0 = m0 + warpM * 32 + i * 16 + g;
        #pragma unroll
        for (int j = 0; j < 8; ++j) {
            const int col = n0 + warpN * 64 + j * 8 + 2 * tq;
            if (r0 < cnt)
                *reinterpret_cast<float2*>(Lg + (size_t)r0 * CDIM + col) =
                    make_float2(acc[i][j][0], acc[i][j][1]);
            if (r0 + 8 < cnt)
                *reinterpret_cast<float2*>(Lg + (size_t)(r0 + 8) * CDIM + col) =
                    make_float2(acc[i][j][2], acc[i][j][3]);
        }
    }
}

// ---------------------------------------------------------------------------
// Kernel 3: softmax + scale by non_end + scatter + log_prob.  [R13 exact]
// ---------------------------------------------------------------------------
__global__ __launch_bounds__(256) void k_softmax(
    const int* __restrict__ Y,
    const float* __restrict__ b_hcw, const float* __restrict__ b_roo,
    float* __restrict__ out)
{
    const int z    = blockIdx.z;
    const int warp = threadIdx.x >> 5;
    const int lane = threadIdx.x & 31;
    const int pos  = blockIdx.x * 8 + warp;
    if (pos >= g_cnt[z]) return;
    const int t = g_list[z][pos];

    const float* __restrict__ bias = (z == 0) ? b_hcw : b_roo;
    const float* Lrow = g_logits[z] + (size_t)pos * CDIM;
    const float4* L4 = reinterpret_cast<const float4*>(Lrow);
    const float4* B4 = reinterpret_cast<const float4*>(bias);

    float4 v[8];
    float mx = -1e30f;
    #pragma unroll
    for (int i = 0; i < 8; ++i) {
        float4 a = L4[lane + 32 * i];
        float4 b = B4[lane + 32 * i];
        a.x += b.x; a.y += b.y; a.z += b.z; a.w += b.w;
        v[i] = a;
        mx = fmaxf(mx, fmaxf(fmaxf(a.x, a.y), fmaxf(a.z, a.w)));
    }
    #pragma unroll
    for (int o = 16; o; o >>= 1) mx = fmaxf(mx, __shfl_xor_sync(0xffffffffu, mx, o));

    float sum = 0.f;
    #pragma unroll
    for (int i = 0; i < 8; ++i) {
        v[i].x = expf(v[i].x - mx); v[i].y = expf(v[i].y - mx);
        v[i].z = expf(v[i].z - mx); v[i].w = expf(v[i].w - mx);
        sum += (v[i].x + v[i].y) + (v[i].z + v[i].w);
    }
    #pragma unroll
    for (int o = 16; o; o >>= 1) sum += __shfl_xor_sync(0xffffffffu, sum, o);

    const float ne = g_nonend[t];
    const float scale = ne / sum;

    float* row = out + NTOK + (size_t)t * OUTW + ((z == 0) ? 2 : 2 + CDIM);
    #pragma unroll
    for (int i = 0; i < 8; ++i) {
        const int c0 = 4 * (lane + 32 * i);
        *reinterpret_cast<float2*>(row + c0)     = make_float2(v[i].x * scale, v[i].y * scale);
        *reinterpret_cast<float2*>(row + c0 + 2) = make_float2(v[i].z * scale, v[i].w * scale);
    }

    if (lane == 0) {
        const int yv = Y[t];
        int idx = yv - 2 - ((z == 0) ? 0 : CDIM);
        idx = min(max(idx, 0), CDIM - 1);
        const float li = Lrow[idx] + bias[idx];
        out[t] = (li - mx) - logf(sum) + logf(ne);
    }
}

// ---------------------------------------------------------------------------
// Launcher
// ---------------------------------------------------------------------------
extern "C" void kernel_launch(void* const* d_in, const int* in_sizes, int n_in,
                              void* d_out, int out_size)
{
    const float* X     = (const float*)d_in[0];
    const int*   pY    = (const int*)d_in[1];
    const int*   Y     = (const int*)d_in[2];
    const float* W_end = (const float*)d_in[3];
    const float* b_end = (const float*)d_in[4];
    const float* W_hcw = (const float*)d_in[5];
    const float* b_hcw = (const float*)d_in[6];
    const float* W_roo = (const float*)d_in[7];
    const float* b_roo = (const float*)d_in[8];
    float* out = (float*)d_out;
    (void)in_sizes; (void)n_in; (void)out_size;

    const int dyn = 128 + NSTAGE * STAGE_SZ;   // 196736
    static bool attr_set = false;
    if (!attr_set) {
        cudaFuncSetAttribute(k_gemm_mma, cudaFuncAttributeMaxDynamicSharedMemorySize, dyn);
        attr_set = true;
    }

    k_reset<<<1, 32>>>();
    k_prep<<<NTOK / 8 + 512, 256>>>(X, pY, W_end, b_end, W_hcw, W_roo, out);
    k_gemm_mma<<<dim3(CDIM / BN, NTOK / BM, 2), 256, dyn>>>();
    k_softmax<<<dim3(NTOK / 8, 1, 2), 256>>>(Y, b_hcw, b_roo, out);
}